// round 15
// baseline (speedup 1.0000x reference)
#include <cuda_runtime.h>
#include <math.h>

// ---------------------------------------------------------------------------
// KAN recommender: layer0 (128 -> 64, cubic B-splines, G=5) -> layer1 (64 -> 1)
// -> sigmoid.  Batch = 1024.
//
// Decomposition:
//   prep_kernel   : fold ssp*coef / sb into transposed weight Wt[i][j][o]
//   layer0_kernel : grid (4 i-tiles x 32 b-tiles); features (8 bases + silu)
//                   in smem, register-tiled fp32 contraction -> d_part
//   final_kernel  : reduce i-tiles + bias0, layer1 splines, reduce over 64,
//                   bias1 + sigmoid -> out
// ---------------------------------------------------------------------------

#define NBATCH 1024
#define IN0    128      // layer0 in_dim
#define OUT0   64       // layer0 out_dim
#define JF     9        // 8 spline bases + 1 silu feature
#define ITILES 4
#define ICHUNK 32       // IN0 / ITILES
#define BROWS  32       // batch rows per CTA

__device__ float d_Wt0[IN0 * JF * OUT0];          // 128*9*64 floats
__device__ float d_part[ITILES * NBATCH * OUT0];  // partial layer0 sums

// ---------------------------------------------------------------------------
// Weight fold + transpose: Wt0[(i*9+j)*64 + o] = j<8 ? ssp0[n]*coef0[n*8+j]
//                                                     : sb0[n],  n = o*128+i
// ---------------------------------------------------------------------------
__global__ void prep_kernel(const float* __restrict__ coef0,
                            const float* __restrict__ sb0,
                            const float* __restrict__ ssp0) {
    int idx = blockIdx.x * blockDim.x + threadIdx.x;
    if (idx >= IN0 * JF * OUT0) return;
    int o  = idx & (OUT0 - 1);
    int ij = idx >> 6;
    int j  = ij % JF;
    int i  = ij / JF;
    int n  = o * IN0 + i;
    d_Wt0[idx] = (j < 8) ? ssp0[n] * coef0[n * 8 + j] : sb0[n];
}

// ---------------------------------------------------------------------------
// Layer0.  blockIdx.x = i-tile (0..3), blockIdx.y = b-tile (0..31), 256 thr.
// ---------------------------------------------------------------------------
__global__ void __launch_bounds__(256) layer0_kernel(
        const int*   __restrict__ uidx,
        const int*   __restrict__ iidx,
        const float* __restrict__ emb_u,
        const float* __restrict__ emb_i,
        const float* __restrict__ grid0) {

    __shared__ float s_kn[ICHUNK][13];                       // 12 knots (pad 13)
    __shared__ float s_rec[ICHUNK][33];                      // 30 recips (pad 33)
    __shared__ __align__(16) float s_feat[ICHUNK * JF * BROWS];

    int tid   = threadIdx.x;
    int itile = blockIdx.x;
    int btile = blockIdx.y;

    // ---- per-i knot extension + reciprocal denominators (1 warp) ----------
    if (tid < ICHUNK) {
        int ig = itile * ICHUNK + tid;
        float g[6];
        #pragma unroll
        for (int m = 0; m < 6; m++) g[m] = grid0[ig * 6 + m];
        float h = (g[5] - g[0]) * 0.2f;
        float kn[12];
        kn[0] = g[0] - 3.f * h; kn[1] = g[0] - 2.f * h; kn[2] = g[0] - h;
        #pragma unroll
        for (int m = 0; m < 6; m++) kn[3 + m] = g[m];
        kn[9] = g[5] + h; kn[10] = g[5] + 2.f * h; kn[11] = g[5] + 3.f * h;
        #pragma unroll
        for (int m = 0; m < 12; m++) s_kn[tid][m] = kn[m];
        int off = 0;
        #pragma unroll
        for (int kk = 1; kk <= 3; kk++) {
            for (int a = 0; a <= 11 - kk; a++)
                s_rec[tid][off + a] = 1.0f / (kn[a + kk] - kn[a]);
            off += 12 - kk;
        }
    }
    __syncthreads();

    // ---- phase A: features for 32 rows x 32 inputs ------------------------
    for (int p = tid; p < BROWS * ICHUNK; p += 256) {
        int il = p & (ICHUNK - 1);
        int r  = p >> 5;
        int b  = btile * BROWS + r;
        int ig = itile * ICHUNK + il;
        float x;
        if (ig < 64) x = emb_u[(long)uidx[b] * 64 + ig];
        else         x = emb_i[(long)iidx[b] * 64 + (ig - 64)];
        float sl = x / (1.0f + __expf(-x));   // silu

        const float* kn = s_kn[il];
        const float* rc = s_rec[il];
        float Bv[11];
        #pragma unroll
        for (int m = 0; m < 11; m++)
            Bv[m] = (x >= kn[m] && x < kn[m + 1]) ? 1.0f : 0.0f;
        #pragma unroll
        for (int m = 0; m < 10; m++)   // kk = 1
            Bv[m] = (x - kn[m]) * rc[m] * Bv[m]
                  + (kn[m + 2] - x) * rc[m + 1] * Bv[m + 1];
        #pragma unroll
        for (int m = 0; m < 9; m++)    // kk = 2
            Bv[m] = (x - kn[m]) * rc[11 + m] * Bv[m]
                  + (kn[m + 3] - x) * rc[11 + m + 1] * Bv[m + 1];
        #pragma unroll
        for (int m = 0; m < 8; m++)    // kk = 3
            Bv[m] = (x - kn[m]) * rc[21 + m] * Bv[m]
                  + (kn[m + 4] - x) * rc[21 + m + 1] * Bv[m + 1];

        #pragma unroll
        for (int j = 0; j < 8; j++)
            s_feat[(il * JF + j) * BROWS + r] = Bv[j];
        s_feat[(il * JF + 8) * BROWS + r] = sl;
    }
    __syncthreads();

    // ---- phase B: contraction, 4 rows x 2 outs per thread -----------------
    int o2 = tid & 31;          // output pair index (outs 2*o2, 2*o2+1)
    int rg = tid >> 5;          // row group (4 rows), == warp id -> broadcast LDS
    float2 acc0 = {0.f, 0.f}, acc1 = {0.f, 0.f}, acc2 = {0.f, 0.f}, acc3 = {0.f, 0.f};

    const float* wbase = d_Wt0 + (itile * ICHUNK) * JF * OUT0 + o2 * 2;

    #pragma unroll 1
    for (int il = 0; il < ICHUNK; il++) {
        #pragma unroll
        for (int j = 0; j < JF; j++) {
            float4 f = *(const float4*)&s_feat[(il * JF + j) * BROWS + rg * 4];
            float2 w = *(const float2*)&wbase[(il * JF + j) * OUT0];
            acc0.x += f.x * w.x; acc0.y += f.x * w.y;
            acc1.x += f.y * w.x; acc1.y += f.y * w.y;
            acc2.x += f.z * w.x; acc2.y += f.z * w.y;
            acc3.x += f.w * w.x; acc3.y += f.w * w.y;
        }
    }

    int b0 = btile * BROWS + rg * 4;
    float2* pp = (float2*)&d_part[((long)itile * NBATCH + b0) * OUT0 + o2 * 2];
    pp[0 * (OUT0 / 2)] = acc0;
    pp[1 * (OUT0 / 2)] = acc1;
    pp[2 * (OUT0 / 2)] = acc2;
    pp[3 * (OUT0 / 2)] = acc3;
}

// ---------------------------------------------------------------------------
// Final: reduce i-tiles + bias0, layer1 splines per (b, i=o), reduce 64,
// bias1 + sigmoid.  4 batch rows per CTA (256 threads, 64 per row).
// ---------------------------------------------------------------------------
__global__ void __launch_bounds__(256) final_kernel(
        const float* __restrict__ bias0,
        const float* __restrict__ grid1,
        const float* __restrict__ coef1,
        const float* __restrict__ sb1,
        const float* __restrict__ ssp1,
        const float* __restrict__ bias1,
        float* __restrict__ out) {

    __shared__ float red[8];
    int tid = threadIdx.x;
    int o   = tid & 63;
    int bs  = tid >> 6;
    int b   = blockIdx.x * 4 + bs;

    float x = bias0[o];
    #pragma unroll
    for (int t = 0; t < ITILES; t++)
        x += d_part[((long)t * NBATCH + b) * OUT0 + o];

    // layer1 spline for input dim o (spline index n = o)
    float g[6];
    #pragma unroll
    for (int m = 0; m < 6; m++) g[m] = grid1[o * 6 + m];
    float h = (g[5] - g[0]) * 0.2f;
    float kn[12];
    kn[0] = g[0] - 3.f * h; kn[1] = g[0] - 2.f * h; kn[2] = g[0] - h;
    #pragma unroll
    for (int m = 0; m < 6; m++) kn[3 + m] = g[m];
    kn[9] = g[5] + h; kn[10] = g[5] + 2.f * h; kn[11] = g[5] + 3.f * h;

    float rc1[11], rc2[10], rc3[9];
    #pragma unroll
    for (int a = 0; a < 11; a++) rc1[a] = 1.0f / (kn[a + 1] - kn[a]);
    #pragma unroll
    for (int a = 0; a < 10; a++) rc2[a] = 1.0f / (kn[a + 2] - kn[a]);
    #pragma unroll
    for (int a = 0; a < 9;  a++) rc3[a] = 1.0f / (kn[a + 3] - kn[a]);

    float Bv[11];
    #pragma unroll
    for (int m = 0; m < 11; m++)
        Bv[m] = (x >= kn[m] && x < kn[m + 1]) ? 1.0f : 0.0f;
    #pragma unroll
    for (int m = 0; m < 10; m++)
        Bv[m] = (x - kn[m]) * rc1[m] * Bv[m] + (kn[m + 2] - x) * rc1[m + 1] * Bv[m + 1];
    #pragma unroll
    for (int m = 0; m < 9; m++)
        Bv[m] = (x - kn[m]) * rc2[m] * Bv[m] + (kn[m + 3] - x) * rc2[m + 1] * Bv[m + 1];
    #pragma unroll
    for (int m = 0; m < 8; m++)
        Bv[m] = (x - kn[m]) * rc3[m] * Bv[m] + (kn[m + 4] - x) * rc3[m + 1] * Bv[m + 1];

    float sl = x / (1.0f + __expf(-x));
    float dot = 0.f;
    #pragma unroll
    for (int j = 0; j < 8; j++) dot += coef1[o * 8 + j] * Bv[j];
    float c = sb1[o] * sl + ssp1[o] * dot;

    // reduce 64 values (2 warps per batch row; warps are row-contiguous)
    #pragma unroll
    for (int s = 16; s > 0; s >>= 1)
        c += __shfl_down_sync(0xffffffffu, c, s);
    int warp = tid >> 5;
    if ((tid & 31) == 0) red[warp] = c;
    __syncthreads();
    if (tid < 4) {
        float z = red[2 * tid] + red[2 * tid + 1] + bias1[0];
        out[blockIdx.x * 4 + tid] = 1.0f / (1.0f + __expf(-z));
    }
}

// ---------------------------------------------------------------------------
extern "C" void kernel_launch(void* const* d_in, const int* in_sizes, int n_in,
                              void* d_out, int out_size) {
    const int*   uidx  = (const int*)  d_in[0];
    const int*   iidx  = (const int*)  d_in[1];
    // d_in[2], d_in[3]: grid_update_num / stop_grid_update_step (unused)
    const float* emb_u = (const float*)d_in[4];
    const float* emb_i = (const float*)d_in[5];
    const float* grid0 = (const float*)d_in[6];
    const float* coef0 = (const float*)d_in[7];
    const float* sb0   = (const float*)d_in[8];
    const float* ssp0  = (const float*)d_in[9];
    const float* bias0 = (const float*)d_in[10];
    const float* grid1 = (const float*)d_in[11];
    const float* coef1 = (const float*)d_in[12];
    const float* sb1   = (const float*)d_in[13];
    const float* ssp1  = (const float*)d_in[14];
    const float* bias1 = (const float*)d_in[15];
    float* out = (float*)d_out;

    prep_kernel<<<(IN0 * JF * OUT0 + 255) / 256, 256>>>(coef0, sb0, ssp0);

    dim3 g1(ITILES, NBATCH / BROWS);   // (4, 32)
    layer0_kernel<<<g1, 256>>>(uidx, iidx, emb_u, emb_i, grid0);

    final_kernel<<<NBATCH / 4, 256>>>(bias0, grid1, coef1, sb1, ssp1, bias1, out);
}